// round 4
// baseline (speedup 1.0000x reference)
#include <cuda_runtime.h>

#define N 512
#define BATCH 256
#define CHUNKS 8                    // chunks per batch row
#define TPB 256
#define GRID (CHUNKS * BATCH)       // 2048 blocks
#define PF 8                        // prefetch depth (float4 per thread)

// Scratch (no device allocs allowed)
__device__ __align__(16) float g_u[N];
__device__ __align__(16) float g_v[N];
__device__ float g_partial2[BATCH][CHUNKS];
__device__ int g_proj_cnt = 0;      // proj blocks completed
__device__ int g_flag     = 0;      // u,v ready (release/acquire via fences)
__device__ int g_done_cnt = 0;      // reduce blocks completed

__global__ void __launch_bounds__(TPB, 4)
fused_kernel(const float* __restrict__ x,
             const float* __restrict__ wh,
             const float* __restrict__ wv,
             const float* __restrict__ bias,
             float* __restrict__ out) {
    const int bid = blockIdx.x;
    const int t   = threadIdx.x;
    const int b   = bid >> 3;        // batch row
    const int c   = bid & (CHUNKS - 1);

    __shared__ float ru[TPB / 32], rv[TPB / 32];
    __shared__ bool  is_last;

    // ----------------------------------------------------------------------
    // Phase 1 (blocks 0..511): u[k] = sum_i wh[i]*cu(i)*cos((2k+1)i pi/2N),
    // same for v. cospif arg numerator (2k+1)*i < 2^24 -> exact fp32.
    // ----------------------------------------------------------------------
    if (bid < N) {
        const int k = bid;
        const float c0 = sqrtf(1.0f / N);
        const float c1 = sqrtf(2.0f / N);
        const float two_k_p1 = (float)(2 * k + 1);
        float su = 0.f, sv = 0.f;
        #pragma unroll
        for (int r = 0; r < N / TPB; ++r) {          // 2 iters
            int i = r * TPB + t;
            float cu = (i == 0) ? c0 : c1;
            float tt = two_k_p1 * (float)i * (1.0f / (2.0f * N));
            float cc = cospif(tt) * cu;
            su = fmaf(wh[i], cc, su);
            sv = fmaf(wv[i], cc, sv);
        }
        #pragma unroll
        for (int o = 16; o > 0; o >>= 1) {
            su += __shfl_down_sync(0xffffffffu, su, o);
            sv += __shfl_down_sync(0xffffffffu, sv, o);
        }
        if ((t & 31) == 0) { ru[t >> 5] = su; rv[t >> 5] = sv; }
        __syncthreads();
        if (t == 0) {
            float fu = 0.f, fv = 0.f;
            #pragma unroll
            for (int w = 0; w < TPB / 32; ++w) { fu += ru[w]; fv += rv[w]; }
            g_u[k] = fu;
            g_v[k] = fv;
            __threadfence();
            int old = atomicAdd(&g_proj_cnt, 1);
            if (old == N - 1) {
                __threadfence();
                *((volatile int*)&g_flag) = 1;       // release u,v
            }
        }
    }

    // ----------------------------------------------------------------------
    // Phase 2: prefetch x (independent of u,v) so DRAM is busy during proj.
    // ----------------------------------------------------------------------
    const int f4_per_row   = (N * N) / 4;            // 65536
    const int f4_per_chunk = f4_per_row / CHUNKS;    // 8192
    const int iters        = f4_per_chunk / TPB;     // 32

    const float4* __restrict__ xr =
        reinterpret_cast<const float4*>(x) + (size_t)b * f4_per_row + c * f4_per_chunk;

    float4 buf[PF];
    #pragma unroll
    for (int p = 0; p < PF; ++p)
        buf[p] = __ldcs(&xr[p * TPB + t]);

    // Acquire u,v. Safe: __launch_bounds__(TPB,4) -> >=592 resident blocks in
    // wave 1, so all 512 proj blocks run without needing spinners to retire.
    if (t == 0) {
        while (*((volatile int*)&g_flag) == 0) __nanosleep(64);
    }
    __syncthreads();
    __threadfence();                                  // acquire fence

    // ----------------------------------------------------------------------
    // Phase 3: streaming weighted reduction.
    // acc += x[b,e] * u[e>>9] * v[e&511]
    // ----------------------------------------------------------------------
    float acc = 0.f;
    #pragma unroll
    for (int p = 0; p < PF; ++p) {
        int f = p * TPB + t;
        int e = (c * f4_per_chunk + f) * 4;
        int k = e >> 9;
        int l = e & 511;                              // l % 4 == 0
        float4 v4 = *reinterpret_cast<const float4*>(&g_v[l]);
        float4 xv = buf[p];
        float dot = fmaf(xv.x, v4.x, fmaf(xv.y, v4.y,
                    fmaf(xv.z, v4.z, xv.w * v4.w)));
        acc = fmaf(g_u[k], dot, acc);
    }
    #pragma unroll 8
    for (int i = PF; i < iters; ++i) {
        int f = i * TPB + t;
        float4 xv = __ldcs(&xr[f]);
        int e = (c * f4_per_chunk + f) * 4;
        int k = e >> 9;
        int l = e & 511;
        float4 v4 = *reinterpret_cast<const float4*>(&g_v[l]);
        float dot = fmaf(xv.x, v4.x, fmaf(xv.y, v4.y,
                    fmaf(xv.z, v4.z, xv.w * v4.w)));
        acc = fmaf(g_u[k], dot, acc);
    }

    // deterministic block reduction
    __shared__ float red[TPB / 32];
    #pragma unroll
    for (int o = 16; o > 0; o >>= 1)
        acc += __shfl_down_sync(0xffffffffu, acc, o);
    if ((t & 31) == 0) red[t >> 5] = acc;
    __syncthreads();
    if (t == 0) {
        float s = 0.f;
        #pragma unroll
        for (int w = 0; w < TPB / 32; ++w) s += red[w];
        g_partial2[b][c] = s;
    }

    // ----------------------------------------------------------------------
    // Phase 4: last block finishes (sigmoid) and resets state for replay.
    // ----------------------------------------------------------------------
    __threadfence();
    if (t == 0) {
        int old = atomicAdd(&g_done_cnt, 1);
        is_last = (old == GRID - 1);
    }
    __syncthreads();
    if (is_last) {
        __threadfence();                              // see all partials
        if (t < BATCH) {
            float r = bias[0];
            #pragma unroll
            for (int cc = 0; cc < CHUNKS; ++cc) r += g_partial2[t][cc];
            out[t] = 1.0f / (1.0f + __expf(-r));
        }
        if (t == 0) {                                 // reset for next replay
            g_done_cnt = 0;
            g_proj_cnt = 0;
            g_flag     = 0;
        }
    }
}

extern "C" void kernel_launch(void* const* d_in, const int* in_sizes, int n_in,
                              void* d_out, int out_size) {
    const float* x    = (const float*)d_in[0];
    const float* wh   = (const float*)d_in[1];
    const float* wv   = (const float*)d_in[2];
    const float* bias = (const float*)d_in[3];
    float* out = (float*)d_out;

    fused_kernel<<<GRID, TPB>>>(x, wh, wv, bias, out);
}

// round 6
// speedup vs baseline: 1.0031x; 1.0031x over previous
#include <cuda_runtime.h>

#define N 512
#define BATCH 256
#define CHUNKS 8                    // chunks per batch row
#define TPB 256
#define GRID (CHUNKS * BATCH)       // 2048 blocks
#define PF 8                        // prefetch depth (float4 per thread)

// Scratch (no device allocs allowed)
__device__ __align__(16) float g_u[N];
__device__ __align__(16) float g_v[N];
__device__ float g_partial2[BATCH][CHUNKS];
__device__ int g_proj_cnt = 0;      // proj blocks completed
__device__ int g_flag     = 0;      // u,v ready (release/acquire via fences)
__device__ int g_done_cnt = 0;      // reduce blocks completed

__global__ void __launch_bounds__(TPB, 4)
fused_kernel(const float* __restrict__ x,
             const float* __restrict__ wh,
             const float* __restrict__ wv,
             const float* __restrict__ bias,
             float* __restrict__ out) {
    const int bid = blockIdx.x;
    const int t   = threadIdx.x;
    const int b   = bid >> 3;        // batch row
    const int c   = bid & (CHUNKS - 1);

    __shared__ float ru[TPB / 32], rv[TPB / 32];
    __shared__ bool  is_last;

    // ----------------------------------------------------------------------
    // Phase 1 (blocks 0..511): u[k] = sum_i wh[i]*cu(i)*cos((2k+1)i pi/2N),
    // same for v. cospif arg numerator (2k+1)*i < 2^24 -> exact fp32.
    // ----------------------------------------------------------------------
    if (bid < N) {
        const int k = bid;
        const float c0 = sqrtf(1.0f / N);
        const float c1 = sqrtf(2.0f / N);
        const float two_k_p1 = (float)(2 * k + 1);
        float su = 0.f, sv = 0.f;
        #pragma unroll
        for (int r = 0; r < N / TPB; ++r) {          // 2 iters
            int i = r * TPB + t;
            float cu = (i == 0) ? c0 : c1;
            float tt = two_k_p1 * (float)i * (1.0f / (2.0f * N));
            float cc = cospif(tt) * cu;
            su = fmaf(wh[i], cc, su);
            sv = fmaf(wv[i], cc, sv);
        }
        #pragma unroll
        for (int o = 16; o > 0; o >>= 1) {
            su += __shfl_down_sync(0xffffffffu, su, o);
            sv += __shfl_down_sync(0xffffffffu, sv, o);
        }
        if ((t & 31) == 0) { ru[t >> 5] = su; rv[t >> 5] = sv; }
        __syncthreads();
        if (t == 0) {
            float fu = 0.f, fv = 0.f;
            #pragma unroll
            for (int w = 0; w < TPB / 32; ++w) { fu += ru[w]; fv += rv[w]; }
            g_u[k] = fu;
            g_v[k] = fv;
            __threadfence();
            int old = atomicAdd(&g_proj_cnt, 1);
            if (old == N - 1) {
                __threadfence();
                *((volatile int*)&g_flag) = 1;       // release u,v
            }
        }
    }

    // ----------------------------------------------------------------------
    // Phase 2: prefetch x (independent of u,v) so DRAM is busy during proj.
    // ----------------------------------------------------------------------
    const int f4_per_row   = (N * N) / 4;            // 65536
    const int f4_per_chunk = f4_per_row / CHUNKS;    // 8192
    const int iters        = f4_per_chunk / TPB;     // 32

    const float4* __restrict__ xr =
        reinterpret_cast<const float4*>(x) + (size_t)b * f4_per_row + c * f4_per_chunk;

    float4 buf[PF];
    #pragma unroll
    for (int p = 0; p < PF; ++p)
        buf[p] = __ldcs(&xr[p * TPB + t]);

    // Acquire u,v. Safe: __launch_bounds__(TPB,4) -> >=592 resident blocks in
    // wave 1, so all 512 proj blocks run without needing spinners to retire.
    if (t == 0) {
        while (*((volatile int*)&g_flag) == 0) __nanosleep(64);
    }
    __syncthreads();
    __threadfence();                                  // acquire fence

    // ----------------------------------------------------------------------
    // Phase 3: streaming weighted reduction.
    // acc += x[b,e] * u[e>>9] * v[e&511]
    // ----------------------------------------------------------------------
    float acc = 0.f;
    #pragma unroll
    for (int p = 0; p < PF; ++p) {
        int f = p * TPB + t;
        int e = (c * f4_per_chunk + f) * 4;
        int k = e >> 9;
        int l = e & 511;                              // l % 4 == 0
        float4 v4 = *reinterpret_cast<const float4*>(&g_v[l]);
        float4 xv = buf[p];
        float dot = fmaf(xv.x, v4.x, fmaf(xv.y, v4.y,
                    fmaf(xv.z, v4.z, xv.w * v4.w)));
        acc = fmaf(g_u[k], dot, acc);
    }
    #pragma unroll 8
    for (int i = PF; i < iters; ++i) {
        int f = i * TPB + t;
        float4 xv = __ldcs(&xr[f]);
        int e = (c * f4_per_chunk + f) * 4;
        int k = e >> 9;
        int l = e & 511;
        float4 v4 = *reinterpret_cast<const float4*>(&g_v[l]);
        float dot = fmaf(xv.x, v4.x, fmaf(xv.y, v4.y,
                    fmaf(xv.z, v4.z, xv.w * v4.w)));
        acc = fmaf(g_u[k], dot, acc);
    }

    // deterministic block reduction
    __shared__ float red[TPB / 32];
    #pragma unroll
    for (int o = 16; o > 0; o >>= 1)
        acc += __shfl_down_sync(0xffffffffu, acc, o);
    if ((t & 31) == 0) red[t >> 5] = acc;
    __syncthreads();
    if (t == 0) {
        float s = 0.f;
        #pragma unroll
        for (int w = 0; w < TPB / 32; ++w) s += red[w];
        g_partial2[b][c] = s;
    }

    // ----------------------------------------------------------------------
    // Phase 4: last block finishes (sigmoid) and resets state for replay.
    // ----------------------------------------------------------------------
    __threadfence();
    if (t == 0) {
        int old = atomicAdd(&g_done_cnt, 1);
        is_last = (old == GRID - 1);
    }
    __syncthreads();
    if (is_last) {
        __threadfence();                              // see all partials
        if (t < BATCH) {
            float r = bias[0];
            #pragma unroll
            for (int cc = 0; cc < CHUNKS; ++cc) r += g_partial2[t][cc];
            out[t] = 1.0f / (1.0f + __expf(-r));
        }
        if (t == 0) {                                 // reset for next replay
            g_done_cnt = 0;
            g_proj_cnt = 0;
            g_flag     = 0;
        }
    }
}

extern "C" void kernel_launch(void* const* d_in, const int* in_sizes, int n_in,
                              void* d_out, int out_size) {
    const float* x    = (const float*)d_in[0];
    const float* wh   = (const float*)d_in[1];
    const float* wv   = (const float*)d_in[2];
    const float* bias = (const float*)d_in[3];
    float* out = (float*)d_out;

    fused_kernel<<<GRID, TPB>>>(x, wh, wv, bias, out);
}